// round 3
// baseline (speedup 1.0000x reference)
#include <cuda_runtime.h>
#include <math.h>

#define C_DIM 1000
#define ALPHA 0.01f
#define EPS_V 1e-15f
#define MAX_ROWS 131072

// Scratch
__device__ float g_Tt[C_DIM * C_DIM];       // transposed T_result (4 MB)
__device__ int   g_hist[C_DIM];             // per-target counts
__device__ int   g_binstart[C_DIM];         // exclusive prefix
__device__ int   g_cursor[C_DIM];           // scatter cursors
__device__ int   g_rows[MAX_ROWS];          // row indices grouped by target
__device__ float g_partials[C_DIM];         // per-target loss partials

// ---------------------------------------------------------------------------
// Kernel 1: Tt[t][c] = T[c][t] + ALPHA*corr[c][t], 128(t) x 32(c) tiles.
// Block (0,0) also zeroes the target histogram.
// ---------------------------------------------------------------------------
__global__ __launch_bounds__(256) void prep_T_kernel(const float* __restrict__ T,
                                                     const float* __restrict__ corr) {
    __shared__ float tile[128][33];   // [t_local][c_local]
    const int c0 = blockIdx.y * 32;
    const int t0 = blockIdx.x * 128;
    const int tid = threadIdx.x;

    if (blockIdx.x == 0 && blockIdx.y == 0) {
        for (int i = tid; i < C_DIM; i += 256) g_hist[i] = 0;
    }

    const int c_local = tid >> 3;   // 0..31
    const int t4base  = tid & 7;    // 0..7
    const int c = c0 + c_local;
    if (c < C_DIM) {
        const float4* Trow = reinterpret_cast<const float4*>(T    + (size_t)c * C_DIM);
        const float4* Crow = reinterpret_cast<const float4*>(corr + (size_t)c * C_DIM);
#pragma unroll
        for (int k = 0; k < 4; k++) {
            int f4 = (t0 >> 2) + t4base + 8 * k;   // float4 index within row
            if (f4 < C_DIM / 4) {
                float4 a = __ldg(&Trow[f4]);
                float4 b = __ldg(&Crow[f4]);
                int tl = (t4base + 8 * k) * 4;
                tile[tl + 0][c_local] = a.x + ALPHA * b.x;
                tile[tl + 1][c_local] = a.y + ALPHA * b.y;
                tile[tl + 2][c_local] = a.z + ALPHA * b.z;
                tile[tl + 3][c_local] = a.w + ALPHA * b.w;
            }
        }
    }
    __syncthreads();

    const int lane = tid & 31;
    const int w    = tid >> 5;      // 8 warps
    const int cc   = c0 + lane;
    if (cc < C_DIM) {
#pragma unroll
        for (int k = 0; k < 16; k++) {
            int tl = w * 16 + k;
            int t  = t0 + tl;
            if (t < C_DIM)
                g_Tt[(size_t)t * C_DIM + cc] = tile[tl][lane];
        }
    }
}

// ---------------------------------------------------------------------------
// Kernel 2: histogram of targets.
// ---------------------------------------------------------------------------
__global__ void hist_kernel(const int* __restrict__ target, int B) {
    for (int i = blockIdx.x * blockDim.x + threadIdx.x; i < B; i += gridDim.x * blockDim.x) {
        int t = target[i];
        t = (t < 0) ? 0 : ((t >= C_DIM) ? C_DIM - 1 : t);
        atomicAdd(&g_hist[t], 1);
    }
}

// ---------------------------------------------------------------------------
// Kernel 3: exclusive scan over 1000 bins (one block, Hillis-Steele).
// ---------------------------------------------------------------------------
__global__ __launch_bounds__(1024) void scan_kernel() {
    __shared__ int sm[1024];
    const int i = threadIdx.x;
    const int h = (i < C_DIM) ? g_hist[i] : 0;
    sm[i] = h;
    __syncthreads();
#pragma unroll
    for (int off = 1; off < 1024; off <<= 1) {
        int add = (i >= off) ? sm[i - off] : 0;
        __syncthreads();
        sm[i] += add;
        __syncthreads();
    }
    if (i < C_DIM) {
        int start = sm[i] - h;     // exclusive
        g_binstart[i] = start;
        g_cursor[i]   = start;
    }
}

// ---------------------------------------------------------------------------
// Kernel 4: scatter row indices into target bins.
// ---------------------------------------------------------------------------
__global__ void scatter_kernel(const int* __restrict__ target, int B) {
    for (int i = blockIdx.x * blockDim.x + threadIdx.x; i < B; i += gridDim.x * blockDim.x) {
        int t = target[i];
        t = (t < 0) ? 0 : ((t >= C_DIM) ? C_DIM - 1 : t);
        int pos = atomicAdd(&g_cursor[t], 1);
        if (pos < MAX_ROWS) g_rows[pos] = i;
    }
}

// ---------------------------------------------------------------------------
// Kernel 5: one block per target. Tt[t] lives in smem; stream rows.
// Per row (one warp): m = max(x); S = sum exp(x-m); D = sum exp(x-m)*Tt[t];
//   ce = (m+log S) - x_t;  beta = exp(x_t-m)/S / (D/S + eps);  contrib = beta*ce.
// ---------------------------------------------------------------------------
__global__ __launch_bounds__(256) void grouped_loss_kernel(
    const float* __restrict__ logits, int B) {
    const int t    = blockIdx.x;
    const int tid  = threadIdx.x;
    const int lane = tid & 31;
    const int warp = tid >> 5;          // 8 warps

    __shared__ float4 sT4[C_DIM / 4];   // 250 float4 = 4 KB
    __shared__ float  wsum[8];

    {
        const float4* src = reinterpret_cast<const float4*>(g_Tt + (size_t)t * C_DIM);
        for (int i = tid; i < C_DIM / 4; i += 256) sT4[i] = src[i];
    }
    const int start = g_binstart[t];
    const int count = g_hist[t];
    __syncthreads();

    // target-dependent extraction constants (uniform across block)
    const int q    = t >> 2;
    const int comp = t & 3;
    const int jt   = q >> 5;
    const int src  = q & 31;

    float wacc = 0.0f;

    for (int idx = warp; idx < count; idx += 8) {
        const int row = g_rows[start + idx];
        const float4* r4 = reinterpret_cast<const float4*>(logits + (size_t)row * C_DIM);

        float4 v[8];
#pragma unroll
        for (int j = 0; j < 8; j++) {
            int i4 = lane + 32 * j;
            if (i4 < 250) v[j] = __ldg(&r4[i4]);
            else          v[j] = make_float4(-INFINITY, -INFINITY, -INFINITY, -INFINITY);
        }

        // warp max
        float m = -INFINITY;
#pragma unroll
        for (int j = 0; j < 8; j++)
            m = fmaxf(m, fmaxf(fmaxf(v[j].x, v[j].y), fmaxf(v[j].z, v[j].w)));
#pragma unroll
        for (int o = 16; o > 0; o >>= 1)
            m = fmaxf(m, __shfl_xor_sync(0xffffffffu, m, o));

        // x_t via uniform shuffle
        float4 vt;
        switch (jt) {
            case 0: vt = v[0]; break; case 1: vt = v[1]; break;
            case 2: vt = v[2]; break; case 3: vt = v[3]; break;
            case 4: vt = v[4]; break; case 5: vt = v[5]; break;
            case 6: vt = v[6]; break; default: vt = v[7]; break;
        }
        float cand = (comp == 0) ? vt.x : (comp == 1) ? vt.y : (comp == 2) ? vt.z : vt.w;
        const float x_t = __shfl_sync(0xffffffffu, cand, src);

        // exp in place + sum + dot with smem Tt row
        float s = 0.0f, d = 0.0f;
#pragma unroll
        for (int j = 0; j < 8; j++) {
            v[j].x = __expf(v[j].x - m);
            v[j].y = __expf(v[j].y - m);
            v[j].z = __expf(v[j].z - m);
            v[j].w = __expf(v[j].w - m);
            s += (v[j].x + v[j].y) + (v[j].z + v[j].w);
            int i4 = lane + 32 * j;
            if (i4 < 250) {
                float4 tv = sT4[i4];
                d += v[j].x * tv.x + v[j].y * tv.y + v[j].z * tv.z + v[j].w * tv.w;
            }
        }
#pragma unroll
        for (int o = 16; o > 0; o >>= 1) {
            s += __shfl_xor_sync(0xffffffffu, s, o);
            d += __shfl_xor_sync(0xffffffffu, d, o);
        }

        if (lane == 0) {
            float lse  = m + logf(s);
            float ce   = lse - x_t;
            float pro1 = __expf(x_t - m) / s;
            float pro2 = d / s;
            wacc += (pro1 / (pro2 + EPS_V)) * ce;
        }
    }

    if (lane == 0) wsum[warp] = wacc;
    __syncthreads();
    if (tid == 0) {
        float sum = 0.0f;
#pragma unroll
        for (int w = 0; w < 8; w++) sum += wsum[w];
        g_partials[t] = sum;
    }
}

// ---------------------------------------------------------------------------
// Kernel 6: deterministic final reduction.
// ---------------------------------------------------------------------------
__global__ __launch_bounds__(256) void final_reduce_kernel(float* __restrict__ out, float invB) {
    __shared__ float sh[256];
    float s = 0.0f;
    for (int i = threadIdx.x; i < C_DIM; i += 256) s += g_partials[i];
    sh[threadIdx.x] = s;
    __syncthreads();
#pragma unroll
    for (int o = 128; o > 0; o >>= 1) {
        if (threadIdx.x < o) sh[threadIdx.x] += sh[threadIdx.x + o];
        __syncthreads();
    }
    if (threadIdx.x == 0) out[0] = sh[0] * invB;
}

// ---------------------------------------------------------------------------
extern "C" void kernel_launch(void* const* d_in, const int* in_sizes, int n_in,
                              void* d_out, int out_size) {
    const float* logits = (const float*)d_in[0];   // [B, C] fp32
    const float* corr   = (const float*)d_in[1];   // [C, C] fp32
    const int*   target = (const int*)d_in[2];     // [B] int32
    const float* T      = (const float*)d_in[3];   // [C, C] fp32

    const int B = in_sizes[2];

    dim3 pgrid((C_DIM + 127) / 128, (C_DIM + 31) / 32);   // 8 x 32
    prep_T_kernel<<<pgrid, 256>>>(T, corr);               // also zeroes g_hist

    hist_kernel<<<256, 256>>>(target, B);
    scan_kernel<<<1, 1024>>>();
    scatter_kernel<<<256, 256>>>(target, B);

    grouped_loss_kernel<<<C_DIM, 256>>>(logits, B);

    final_reduce_kernel<<<1, 256>>>((float*)d_out, 1.0f / (float)B);
}